// round 2
// baseline (speedup 1.0000x reference)
#include <cuda_runtime.h>
#include <cuda_bf16.h>

// Problem shape (fixed by the dataset)
#define BB 32
#define TT 2048
#define DD 512
#define D4 (DD / 4)          // 128 float4 per (b,t) row
#define NCHUNK 32
#define CHUNK (TT / NCHUNK)  // 64 timesteps per block

// Scratch (device globals — no allocation allowed in kernel_launch)
__device__ float4 g_part_p[BB * NCHUNK * D4];   // per-(b,chunk,d4) masked sum of preds
__device__ float4 g_part_t[BB * NCHUNK * D4];   // per-(b,chunk,d4) masked sum of targets
__device__ float  g_wl[BB * NCHUNK];            // per-block word-loss partial
__device__ float  g_sent[BB];                   // per-b sentence-loss (mean over D)

__device__ __forceinline__ float sl1(float d) {
    float ad = fabsf(d);
    return (ad < 1.0f) ? (0.5f * d * d) : (ad - 0.5f);
}

__device__ __forceinline__ float block_reduce_128(float v) {
    // 128 threads = 4 warps
    #pragma unroll
    for (int o = 16; o > 0; o >>= 1) v += __shfl_down_sync(0xffffffffu, v, o);
    __shared__ float s[4];
    int w = threadIdx.x >> 5, l = threadIdx.x & 31;
    if (l == 0) s[w] = v;
    __syncthreads();
    if (threadIdx.x == 0) v = s[0] + s[1] + s[2] + s[3];
    return v;  // valid only on thread 0
}

// ---------------------------------------------------------------------------
// Pass 1: stream preds/targets once. grid = BB*NCHUNK, block = 128.
// Thread tid owns float4 column tid (d = 4*tid .. 4*tid+3).
// ---------------------------------------------------------------------------
__global__ __launch_bounds__(128) void pass1(const float4* __restrict__ p,
                                             const float4* __restrict__ q,
                                             const int* __restrict__ lens) {
    int b   = blockIdx.x / NCHUNK;
    int c   = blockIdx.x % NCHUNK;
    int tid = threadIdx.x;

    int len = lens[b];
    int t0  = c * CHUNK;
    int t1  = min(t0 + CHUNK, len);

    float4 sp = make_float4(0.f, 0.f, 0.f, 0.f);
    float4 st = make_float4(0.f, 0.f, 0.f, 0.f);
    float  wl = 0.f;

    const float4* __restrict__ pp = p + (size_t)b * TT * D4 + tid;
    const float4* __restrict__ pq = q + (size_t)b * TT * D4 + tid;

    #pragma unroll 4
    for (int t = t0; t < t1; ++t) {
        float4 a  = __ldg(pp + (size_t)t * D4);
        float4 bt = __ldg(pq + (size_t)t * D4);
        sp.x += a.x; sp.y += a.y; sp.z += a.z; sp.w += a.w;
        st.x += bt.x; st.y += bt.y; st.z += bt.z; st.w += bt.w;
        wl += sl1(a.x - bt.x) + sl1(a.y - bt.y) + sl1(a.z - bt.z) + sl1(a.w - bt.w);
    }

    int pi = (b * NCHUNK + c) * D4 + tid;
    g_part_p[pi] = sp;
    g_part_t[pi] = st;

    float tot = block_reduce_128(wl);
    if (threadIdx.x == 0) g_wl[b * NCHUNK + c] = tot;
}

// ---------------------------------------------------------------------------
// Pass 2: per-b sentence loss. grid = BB, block = 128.
// ---------------------------------------------------------------------------
__global__ __launch_bounds__(128) void pass2(const int* __restrict__ lens) {
    int b   = blockIdx.x;
    int tid = threadIdx.x;

    float4 sp = make_float4(0.f, 0.f, 0.f, 0.f);
    float4 st = make_float4(0.f, 0.f, 0.f, 0.f);
    #pragma unroll
    for (int c = 0; c < NCHUNK; ++c) {
        float4 a  = g_part_p[(b * NCHUNK + c) * D4 + tid];
        float4 bt = g_part_t[(b * NCHUNK + c) * D4 + tid];
        sp.x += a.x; sp.y += a.y; sp.z += a.z; sp.w += a.w;
        st.x += bt.x; st.y += bt.y; st.z += bt.z; st.w += bt.w;
    }
    float inv_len = 1.0f / (float)lens[b];
    float v = sl1((sp.x - st.x) * inv_len)
            + sl1((sp.y - st.y) * inv_len)
            + sl1((sp.z - st.z) * inv_len)
            + sl1((sp.w - st.w) * inv_len);

    float tot = block_reduce_128(v);
    if (threadIdx.x == 0) g_sent[b] = tot / (float)DD;
}

// ---------------------------------------------------------------------------
// Pass 3: final fold. grid = 1, block = 128.
// ---------------------------------------------------------------------------
__global__ __launch_bounds__(128) void pass3(const int* __restrict__ lens,
                                             float* __restrict__ out) {
    int tid = threadIdx.x;

    float wl = 0.f;
    #pragma unroll
    for (int i = tid; i < BB * NCHUNK; i += 128) wl += g_wl[i];

    float sent = 0.f;
    int   lsum = 0;
    if (tid < BB) { sent = g_sent[tid]; lsum = lens[tid]; }

    float wl_tot   = block_reduce_128(wl);
    __syncthreads();
    float sent_tot = block_reduce_128(sent);
    __syncthreads();
    float len_tot  = block_reduce_128((float)lsum);

    if (tid == 0) {
        float n_valid   = len_tot * (float)DD;
        float word_loss = wl_tot / n_valid;
        out[0] = word_loss + sent_tot / (float)BB;
    }
}

extern "C" void kernel_launch(void* const* d_in, const int* in_sizes, int n_in,
                              void* d_out, int out_size) {
    const float4* preds   = (const float4*)d_in[0];
    const float4* targets = (const float4*)d_in[1];
    const int*    lens    = (const int*)d_in[2];
    float*        out     = (float*)d_out;

    pass1<<<BB * NCHUNK, 128>>>(preds, targets, lens);
    pass2<<<BB, 128>>>(lens);
    pass3<<<1, 128>>>(lens, out);
}

// round 4
// speedup vs baseline: 1.6836x; 1.6836x over previous
#include <cuda_runtime.h>
#include <cuda_bf16.h>

// Problem shape (fixed by the dataset)
#define BB 32
#define TT 2048
#define DD 512
#define D4 (DD / 4)            // 128 float4 per (b,t) row
#define NCHUNK 128
#define CHUNK (TT / NCHUNK)    // 16 timesteps per block

// Scratch (device globals — no allocation allowed in kernel_launch)
__device__ float4 g_part_d[BB * NCHUNK * D4];   // per-(b,chunk,d4) masked sum of (p - t)
__device__ float  g_wl[BB * NCHUNK];            // per-block word-loss partial
__device__ float  g_sent[BB * 4];               // per-(b, d-slice) sentence partial (sum of sl1)

__device__ __forceinline__ float sl1(float d) {
    float ad = fabsf(d);
    return (ad < 1.0f) ? (0.5f * d * d) : (ad - 0.5f);
}

// ---------------------------------------------------------------------------
// Pass 1: stream preds/targets once. grid = BB*NCHUNK = 4096, block = 128.
// Thread tid owns float4 column tid (d = 4*tid .. 4*tid+3).
// ---------------------------------------------------------------------------
__global__ __launch_bounds__(128) void pass1(const float4* __restrict__ p,
                                             const float4* __restrict__ q,
                                             const int* __restrict__ lens) {
    int b   = blockIdx.x >> 7;        // / NCHUNK
    int c   = blockIdx.x & (NCHUNK - 1);
    int tid = threadIdx.x;

    int len = lens[b];
    int t0  = c * CHUNK;
    int t1  = min(t0 + CHUNK, len);

    float4 sd = make_float4(0.f, 0.f, 0.f, 0.f);
    float  wl = 0.f;

    const float4* __restrict__ pp = p + (size_t)b * TT * D4 + tid;
    const float4* __restrict__ pq = q + (size_t)b * TT * D4 + tid;

    #pragma unroll 8
    for (int t = t0; t < t1; ++t) {
        float4 a  = __ldg(pp + (size_t)t * D4);
        float4 bt = __ldg(pq + (size_t)t * D4);
        float dx = a.x - bt.x, dy = a.y - bt.y, dz = a.z - bt.z, dw = a.w - bt.w;
        sd.x += dx; sd.y += dy; sd.z += dz; sd.w += dw;
        wl += sl1(dx) + sl1(dy) + sl1(dz) + sl1(dw);
    }

    g_part_d[(b * NCHUNK + c) * D4 + tid] = sd;

    // block-reduce word loss (4 warps)
    #pragma unroll
    for (int o = 16; o > 0; o >>= 1) wl += __shfl_down_sync(0xffffffffu, wl, o);
    __shared__ float s[4];
    if ((tid & 31) == 0) s[tid >> 5] = wl;
    __syncthreads();
    if (tid == 0) g_wl[b * NCHUNK + c] = s[0] + s[1] + s[2] + s[3];
}

// ---------------------------------------------------------------------------
// Pass 2: per-(b, d-slice) sentence partial. grid = BB*4 = 128, block = 128.
// Each block handles 32 float4 columns; 4 rows of 32 threads split the 128 chunks.
// ---------------------------------------------------------------------------
__global__ __launch_bounds__(128) void pass2(const int* __restrict__ lens) {
    int b     = blockIdx.x >> 2;
    int slice = blockIdx.x & 3;
    int tid   = threadIdx.x;
    int col   = slice * 32 + (tid & 31);   // float4 column index in [0,128)
    int r     = tid >> 5;                  // chunk-lane 0..3

    float4 sd = make_float4(0.f, 0.f, 0.f, 0.f);
    const float4* __restrict__ base = g_part_d + (size_t)b * NCHUNK * D4 + col;
    #pragma unroll 8
    for (int c = r; c < NCHUNK; c += 4) {
        float4 a = base[(size_t)c * D4];
        sd.x += a.x; sd.y += a.y; sd.z += a.z; sd.w += a.w;
    }

    __shared__ float4 sh[128];
    sh[tid] = sd;
    __syncthreads();

    if (tid < 32) {
        float4 a0 = sh[tid], a1 = sh[tid + 32], a2 = sh[tid + 64], a3 = sh[tid + 96];
        float inv_len = 1.0f / (float)lens[b];
        float v = sl1((a0.x + a1.x + a2.x + a3.x) * inv_len)
                + sl1((a0.y + a1.y + a2.y + a3.y) * inv_len)
                + sl1((a0.z + a1.z + a2.z + a3.z) * inv_len)
                + sl1((a0.w + a1.w + a2.w + a3.w) * inv_len);
        #pragma unroll
        for (int o = 16; o > 0; o >>= 1) v += __shfl_down_sync(0xffffffffu, v, o);
        if (tid == 0) g_sent[blockIdx.x] = v;
    }
}

// ---------------------------------------------------------------------------
// Pass 3: final fold. grid = 1, block = 256.
// ---------------------------------------------------------------------------
__global__ __launch_bounds__(256) void pass3(const int* __restrict__ lens,
                                             float* __restrict__ out) {
    int tid = threadIdx.x;

    float wl = 0.f;
    #pragma unroll
    for (int i = tid; i < BB * NCHUNK; i += 256) wl += g_wl[i];

    float sent = (tid < BB * 4) ? g_sent[tid] : 0.f;
    float lsum = (tid < BB) ? (float)lens[tid] : 0.f;

    __shared__ float swl[8], ssn[8], sln[8];
    float a = wl, bv = sent, cv = lsum;
    #pragma unroll
    for (int o = 16; o > 0; o >>= 1) {
        a  += __shfl_down_sync(0xffffffffu, a,  o);
        bv += __shfl_down_sync(0xffffffffu, bv, o);
        cv += __shfl_down_sync(0xffffffffu, cv, o);
    }
    int w = tid >> 5;
    if ((tid & 31) == 0) { swl[w] = a; ssn[w] = bv; sln[w] = cv; }
    __syncthreads();

    if (tid == 0) {
        float wl_tot = 0.f, sn_tot = 0.f, ln_tot = 0.f;
        #pragma unroll
        for (int i = 0; i < 8; ++i) { wl_tot += swl[i]; sn_tot += ssn[i]; ln_tot += sln[i]; }
        float n_valid   = ln_tot * (float)DD;
        float word_loss = wl_tot / n_valid;
        float sent_loss = (sn_tot / (float)DD);   // Σ_b mean_d
        out[0] = word_loss + sent_loss / (float)BB;
    }
}

extern "C" void kernel_launch(void* const* d_in, const int* in_sizes, int n_in,
                              void* d_out, int out_size) {
    const float4* preds   = (const float4*)d_in[0];
    const float4* targets = (const float4*)d_in[1];
    const int*    lens    = (const int*)d_in[2];
    float*        out     = (float*)d_out;

    pass1<<<BB * NCHUNK, 128>>>(preds, targets, lens);
    pass2<<<BB * 4, 128>>>(lens);
    pass3<<<1, 256>>>(lens, out);
}